// round 5
// baseline (speedup 1.0000x reference)
#include <cuda_runtime.h>
#include <cstdint>

#define B_       32
#define T_       4096
#define H_       512
#define GRID_    128
#define THREADS_ 512
#define KW_      32

// persistent device state (re-initialized each launch by init_kernel)
__device__ float    g_h[4][H_ * B_];   // 4-deep h ring, layout [k][b]
__device__ float    g_xT[T_ * B_];     // x transposed to [t][b]
__device__ unsigned g_flag[GRID_];     // per-CTA: steps completed (release)
__device__ unsigned g_count;           // aggregate arrivals
__device__ unsigned g_gen;             // lagged global generation

__device__ __forceinline__ float ldcg_f(const float* p) {
    float v; asm volatile("ld.global.cg.f32 %0, [%1];" : "=f"(v) : "l"(p)); return v;
}
__device__ __forceinline__ void stcg_f(float* p, float v) {
    asm volatile("st.global.cg.f32 [%0], %1;" :: "l"(p), "f"(v));
}
__device__ __forceinline__ unsigned ld_acq(const unsigned* p) {
    unsigned v; asm volatile("ld.global.acquire.gpu.u32 %0, [%1];" : "=r"(v) : "l"(p)); return v;
}
__device__ __forceinline__ void st_rel(unsigned* p, unsigned v) {
    asm volatile("st.global.release.gpu.u32 [%0], %1;" :: "l"(p), "r"(v));
}
__device__ __forceinline__ unsigned atom_add_acqrel(unsigned* p, unsigned v) {
    unsigned old;
    asm volatile("atom.acq_rel.gpu.global.add.u32 %0, [%1], %2;"
                 : "=r"(old) : "l"(p), "r"(v));
    return old;
}
__device__ __forceinline__ void ffma2(unsigned long long& a,
                                      unsigned long long w,
                                      unsigned long long h) {
    asm("fma.rn.f32x2 %0, %1, %2, %0;" : "+l"(a) : "l"(w), "l"(h));
}
__device__ __forceinline__ float fsig(float x) {
    float e = __expf(-x);
    return __fdividef(1.0f, 1.0f + e);
}
__device__ __forceinline__ float ftanh(float x) {
    float e = __expf(2.0f * x);
    return 1.0f - __fdividef(2.0f, 1.0f + e);
}

__global__ void init_kernel(const float* __restrict__ x) {
    int idx = blockIdx.x * blockDim.x + threadIdx.x;
    int stride = gridDim.x * blockDim.x;
    if (idx < H_ * B_) g_h[3][idx] = 0.0f;           // h(-1) = 0 lives in buf 3
    if (idx < GRID_)   g_flag[idx] = 0u;
    for (int i = idx; i < T_ * B_; i += stride) {
        int t = i >> 5, b = i & 31;
        g_xT[i] = x[(size_t)b * T_ + t];
    }
    if (idx == 0) { g_count = 0u; g_gen = 0u; }
}

__global__ void __launch_bounds__(THREADS_, 1) lstm_kernel(
    const float* __restrict__ Wih,
    const float* __restrict__ Whh,
    const float* __restrict__ bih,
    const float* __restrict__ bhh,
    float* __restrict__ out,
    int write_final)
{
    extern __shared__ float smem[];
    float* sW    = smem;                 // [k][16 r] : 8192 floats (32 KB)
    float* sPart = smem + 16 * H_;       // double buffered: 2 x 8192 floats
    float* sOut  = smem + 16 * H_ + 16384; // [32 b][4 u]

    const int tid  = threadIdx.x;
    const int warp = tid >> 5;
    const int lane = tid & 31;
    const int u0   = blockIdx.x * 4;

    // W_hh slice (16 rows x 512 k) into smem, k-major. sW[k*16+r], r=q*4+l.
    for (int i = tid; i < 16 * H_; i += THREADS_) {
        int r = i & 15, k = i >> 4, q = r >> 2, l = r & 3;
        sW[k * 16 + r] = Whh[(size_t)(q * H_ + u0 + l) * H_ + k];
    }

    const int u_l = tid >> 5;   // valid for tid<128
    const int b   = tid & 31;
    float bias[4], wih[4];
    float h_loc = 0.0f, c_loc = 0.0f;
    if (tid < 128) {
#pragma unroll
        for (int q = 0; q < 4; q++) {
            int j = q * H_ + u0 + u_l;
            bias[q] = bih[j] + bhh[j];
            wih[q]  = Wih[j];
        }
    }
    __syncthreads();

    const int kbase = warp * KW_;

    for (int t = 0; t < T_; t++) {
        // ---- wait for this warp's 8 producer CTAs to publish h(t-1) ----
        if (lane < 8) {
            const unsigned* f = &g_flag[(warp << 3) + lane];
            while (ld_acq(f) < (unsigned)t) { }
        }
        __syncwarp();

        float xv = 0.0f;
        if (tid < 128) xv = g_xT[t * B_ + b];

        // ---- GEMM partials: warp covers k in [kbase, kbase+32) ----
        const float* hsrc = &g_h[(t + 3) & 3][kbase * B_ + lane];
        float hreg[KW_];
#pragma unroll
        for (int kk = 0; kk < KW_; kk++) hreg[kk] = ldcg_f(hsrc + kk * B_);

        unsigned long long acc[8];
#pragma unroll
        for (int r = 0; r < 8; r++) acc[r] = 0ULL;
#pragma unroll
        for (int kk = 0; kk < KW_; kk++) {
            unsigned long long hh;
            asm("mov.b64 %0, {%1, %1};" : "=l"(hh) : "f"(hreg[kk]));
            const ulonglong2* wp = (const ulonglong2*)(sW + (kbase + kk) * 16);
            ulonglong2 a0 = wp[0], a1 = wp[1], a2 = wp[2], a3 = wp[3];
            ffma2(acc[0], a0.x, hh); ffma2(acc[1], a0.y, hh);
            ffma2(acc[2], a1.x, hh); ffma2(acc[3], a1.y, hh);
            ffma2(acc[4], a2.x, hh); ffma2(acc[5], a2.y, hh);
            ffma2(acc[6], a3.x, hh); ffma2(acc[7], a3.y, hh);
        }
        float* sP = sPart + (t & 1) * 8192;
#pragma unroll
        for (int r = 0; r < 8; r++) {
            float lo, hi;
            asm("mov.b64 {%0, %1}, %2;" : "=f"(lo), "=f"(hi) : "l"(acc[r]));
            sP[(warp * 16 + 2 * r)     * 32 + lane] = lo;
            sP[(warp * 16 + 2 * r + 1) * 32 + lane] = hi;
        }
        __syncthreads();   // the ONLY full-CTA sync per step

        // warps 4..15 immediately continue to step t+1 (overlap Phase B)
        if (tid < 128) {
            float g4[4];
#pragma unroll
            for (int q = 0; q < 4; q++) {
                int r = q * 4 + u_l;
                float s0 = 0.f, s1 = 0.f, s2 = 0.f, s3 = 0.f;
#pragma unroll
                for (int w = 0; w < 16; w += 4) {
                    s0 += sP[((w + 0) * 16 + r) * 32 + b];
                    s1 += sP[((w + 1) * 16 + r) * 32 + b];
                    s2 += sP[((w + 2) * 16 + r) * 32 + b];
                    s3 += sP[((w + 3) * 16 + r) * 32 + b];
                }
                g4[q] = fmaf(xv, wih[q], bias[q]) + ((s0 + s1) + (s2 + s3));
            }
            float is = fsig(g4[0]);
            float fs = fsig(g4[1]);
            float gs = ftanh(g4[2]);
            float os = fsig(g4[3]);

            float cn = fs * c_loc + is * gs;
            float hn = os * ftanh(cn);
            h_loc = 0.5f * (h_loc + hn);
            c_loc = 0.5f * (c_loc + cn);

            // lagged backpressure: h(t) overwrites h(t-4), read during step t-3
            if (t >= 3) {
                unsigned need = (unsigned)(t - 2);
                while (ld_acq(&g_gen) < need) { }
            }
            stcg_f(&g_h[t & 3][(u0 + u_l) * B_ + b], h_loc);
            sOut[b * 4 + u_l] = h_loc;

            if (write_final && t == T_ - 1) {
                float* o2 = out + (size_t)B_ * T_ * H_;
                o2[b * (2 * H_) + u0 + u_l]      = h_loc;
                o2[b * (2 * H_) + H_ + u0 + u_l] = c_loc;
            }

            asm volatile("bar.sync 1, 128;" ::: "memory");

            if (tid == 0) {
                st_rel(&g_flag[blockIdx.x], (unsigned)(t + 1));
                unsigned old = atom_add_acqrel(&g_count, 1u);
                if (old + 1u == (unsigned)GRID_ * (unsigned)(t + 1))
                    st_rel(&g_gen, (unsigned)(t + 1));
            }
            if (tid < 32) {   // coalesced v4 output store
                const float4 v = *(const float4*)(sOut + tid * 4);
                float* dst = out + ((size_t)tid * T_ + t) * H_ + u0;
                asm volatile("st.global.cs.v4.f32 [%0], {%1,%2,%3,%4};"
                             :: "l"(dst), "f"(v.x), "f"(v.y), "f"(v.z), "f"(v.w));
            }
        }
    }
}

extern "C" void kernel_launch(void* const* d_in, const int* in_sizes, int n_in,
                              void* d_out, int out_size)
{
    const float* x   = (const float*)d_in[0];
    const float* Wih = (const float*)d_in[1];
    const float* Whh = (const float*)d_in[2];
    const float* bih = (const float*)d_in[3];
    const float* bhh = (const float*)d_in[4];
    float* out = (float*)d_out;

    int need = B_ * T_ * H_ + B_ * 2 * H_;
    int write_final = (out_size >= need) ? 1 : 0;

    const int smem_bytes = (16 * H_ + 16384 + 128) * sizeof(float);
    static int smem_set = 0;
    if (!smem_set) {
        cudaFuncSetAttribute(lstm_kernel,
                             cudaFuncAttributeMaxDynamicSharedMemorySize,
                             smem_bytes);
        smem_set = 1;
    }

    init_kernel<<<256, 512>>>(x);
    lstm_kernel<<<GRID_, THREADS_, smem_bytes>>>(Wih, Whh, bih, bhh, out, write_final);
}

// round 6
// speedup vs baseline: 2.9256x; 2.9256x over previous
#include <cuda_runtime.h>
#include <cstdint>

#define B_       32
#define T_       4096
#define H_       512
#define GRID_    128
#define THREADS_ 512
#define KW_      32

// persistent device state (re-initialized each launch by init_kernel)
__device__ float    g_h[2][H_ * B_];   // double-buffered h, layout [k][b]
__device__ float    g_xT[T_ * B_];     // x transposed to [t][b]
__device__ unsigned g_count;           // completed-step arrivals (red.add)

__device__ __forceinline__ float ldcg_f(const float* p) {
    float v; asm volatile("ld.global.cg.f32 %0, [%1];" : "=f"(v) : "l"(p)); return v;
}
__device__ __forceinline__ void stcg_f(float* p, float v) {
    asm volatile("st.global.cg.f32 [%0], %1;" :: "l"(p), "f"(v));
}
__device__ __forceinline__ unsigned ld_acq(const unsigned* p) {
    unsigned v; asm volatile("ld.acquire.gpu.global.u32 %0, [%1];" : "=r"(v) : "l"(p)); return v;
}
__device__ __forceinline__ void red_rel_add1(unsigned* p) {
    asm volatile("red.release.gpu.global.add.u32 [%0], 1;" :: "l"(p));
}
__device__ __forceinline__ unsigned ld_acq_cta(const unsigned* p) {
    unsigned v; asm volatile("ld.acquire.cta.u32 %0, [%1];" : "=r"(v) : "l"(p)); return v;
}
__device__ __forceinline__ void st_rel_cta(unsigned* p, unsigned v) {
    asm volatile("st.release.cta.u32 [%0], %1;" :: "l"(p), "r"(v));
}
__device__ __forceinline__ void ffma2(unsigned long long& a,
                                      unsigned long long w,
                                      unsigned long long h) {
    asm("fma.rn.f32x2 %0, %1, %2, %0;" : "+l"(a) : "l"(w), "l"(h));
}
__device__ __forceinline__ float fsig(float x) {
    float e = __expf(-x);
    return __fdividef(1.0f, 1.0f + e);
}
__device__ __forceinline__ float ftanh(float x) {
    float e = __expf(2.0f * x);
    return 1.0f - __fdividef(2.0f, 1.0f + e);
}

__global__ void init_kernel(const float* __restrict__ x) {
    int idx = blockIdx.x * blockDim.x + threadIdx.x;
    int stride = gridDim.x * blockDim.x;
    if (idx < H_ * B_) g_h[0][idx] = 0.0f;
    for (int i = idx; i < T_ * B_; i += stride) {
        int t = i >> 5, b = i & 31;
        g_xT[i] = x[(size_t)b * T_ + t];
    }
    if (idx == 0) g_count = 0u;
}

__global__ void __launch_bounds__(THREADS_, 1) lstm_kernel(
    const float* __restrict__ Wih,
    const float* __restrict__ Whh,
    const float* __restrict__ bih,
    const float* __restrict__ bhh,
    float* __restrict__ out,
    int write_final)
{
    extern __shared__ float smem[];
    float* sW    = smem;                   // [k][16 r]       : 8192 floats
    float* sPart = smem + 16 * H_;         // double-buffered : 2 x 8192 floats
    float* sOut  = smem + 16 * H_ + 16384; // [32 b][4 u]     : 128 floats
    __shared__ unsigned s_gen;             // step token relay

    const int tid  = threadIdx.x;
    const int warp = tid >> 5;
    const int lane = tid & 31;
    const int u0   = blockIdx.x * 4;

    // W_hh slice (16 rows x 512 k) into smem, k-major. sW[k*16+r], r=q*4+l.
    for (int i = tid; i < 16 * H_; i += THREADS_) {
        int r = i & 15, k = i >> 4, q = r >> 2, l = r & 3;
        sW[k * 16 + r] = Whh[(size_t)(q * H_ + u0 + l) * H_ + k];
    }

    const int u_l = tid >> 5;  // valid for tid<128
    const int b   = tid & 31;
    float bias[4], wih[4];
    float h_loc = 0.0f, c_loc = 0.0f;
    if (tid < 128) {
#pragma unroll
        for (int q = 0; q < 4; q++) {
            int j = q * H_ + u0 + u_l;
            bias[q] = bih[j] + bhh[j];
            wih[q]  = Wih[j];
        }
    }
    if (tid == 0) s_gen = 0u;
    __syncthreads();

    const int kbase = warp * KW_;

    for (int t = 0; t < T_; t++) {
        const int p = t & 1;

        // ---- step gate: warp 4 polls global once per CTA, relays via smem ----
        if (warp == 4) {
            if (lane == 0) {
                const unsigned need = (unsigned)(GRID_) * (unsigned)t;
                while (ld_acq(&g_count) < need) { }
                st_rel_cta(&s_gen, (unsigned)t);
            }
            __syncwarp();
        } else {
            while (ld_acq_cta(&s_gen) < (unsigned)t) { }
        }

        float xv = 0.0f;
        if (tid < 128) xv = g_xT[t * B_ + b];

        // ---- GEMM partials: warp covers k in [kbase, kbase+32) ----
        const float* hsrc = &g_h[p][kbase * B_ + lane];
        float hreg[KW_];
#pragma unroll
        for (int kk = 0; kk < KW_; kk++) hreg[kk] = ldcg_f(hsrc + kk * B_);

        unsigned long long acc[8];
#pragma unroll
        for (int r = 0; r < 8; r++) acc[r] = 0ULL;
#pragma unroll
        for (int kk = 0; kk < KW_; kk++) {
            unsigned long long hh;
            asm("mov.b64 %0, {%1, %1};" : "=l"(hh) : "f"(hreg[kk]));
            const ulonglong2* wp = (const ulonglong2*)(sW + (kbase + kk) * 16);
            ulonglong2 a0 = wp[0], a1 = wp[1], a2 = wp[2], a3 = wp[3];
            ffma2(acc[0], a0.x, hh); ffma2(acc[1], a0.y, hh);
            ffma2(acc[2], a1.x, hh); ffma2(acc[3], a1.y, hh);
            ffma2(acc[4], a2.x, hh); ffma2(acc[5], a2.y, hh);
            ffma2(acc[6], a3.x, hh); ffma2(acc[7], a3.y, hh);
        }
        float* sP = sPart + p * 8192;
#pragma unroll
        for (int r = 0; r < 8; r++) {
            float lo, hi;
            asm("mov.b64 {%0, %1}, %2;" : "=f"(lo), "=f"(hi) : "l"(acc[r]));
            sP[(warp * 16 + 2 * r)     * 32 + lane] = lo;
            sP[(warp * 16 + 2 * r + 1) * 32 + lane] = hi;
        }

        if (warp >= 4) {
            // producers: signal partials ready, run ahead to step t+1
            asm volatile("bar.arrive 2, %0;" :: "n"(THREADS_) : "memory");
        } else {
            // consumers: wait for all 16 warps' partials
            asm volatile("bar.sync 2, %0;" :: "n"(THREADS_) : "memory");

            float g4[4];
#pragma unroll
            for (int q = 0; q < 4; q++) {
                int r = q * 4 + u_l;
                float s0 = 0.f, s1 = 0.f, s2 = 0.f, s3 = 0.f;
#pragma unroll
                for (int w = 0; w < 16; w += 4) {
                    s0 += sP[((w + 0) * 16 + r) * 32 + b];
                    s1 += sP[((w + 1) * 16 + r) * 32 + b];
                    s2 += sP[((w + 2) * 16 + r) * 32 + b];
                    s3 += sP[((w + 3) * 16 + r) * 32 + b];
                }
                g4[q] = fmaf(xv, wih[q], bias[q]) + ((s0 + s1) + (s2 + s3));
            }
            float is = fsig(g4[0]);
            float fs = fsig(g4[1]);
            float gs = ftanh(g4[2]);
            float os = fsig(g4[3]);

            float cn = fs * c_loc + is * gs;
            float hn = os * ftanh(cn);
            h_loc = 0.5f * (h_loc + hn);
            c_loc = 0.5f * (c_loc + cn);

            stcg_f(&g_h[p ^ 1][(u0 + u_l) * B_ + b], h_loc);
            sOut[b * 4 + u_l] = h_loc;

            if (write_final && t == T_ - 1) {
                float* o2 = out + (size_t)B_ * T_ * H_;
                o2[b * (2 * H_) + u0 + u_l]      = h_loc;
                o2[b * (2 * H_) + H_ + u0 + u_l] = c_loc;
            }

            // order all 4 consumer warps' h stores before the release
            asm volatile("bar.sync 1, 128;" ::: "memory");
            if (tid == 0) red_rel_add1(&g_count);

            if (tid < 32) {  // coalesced v4 output store (off critical path)
                const float4 v = *(const float4*)(sOut + tid * 4);
                float* dst = out + ((size_t)tid * T_ + t) * H_ + u0;
                asm volatile("st.global.cs.v4.f32 [%0], {%1,%2,%3,%4};"
                             :: "l"(dst), "f"(v.x), "f"(v.y), "f"(v.z), "f"(v.w));
            }
        }
    }
}

extern "C" void kernel_launch(void* const* d_in, const int* in_sizes, int n_in,
                              void* d_out, int out_size)
{
    const float* x   = (const float*)d_in[0];
    const float* Wih = (const float*)d_in[1];
    const float* Whh = (const float*)d_in[2];
    const float* bih = (const float*)d_in[3];
    const float* bhh = (const float*)d_in[4];
    float* out = (float*)d_out;

    int need = B_ * T_ * H_ + B_ * 2 * H_;
    int write_final = (out_size >= need) ? 1 : 0;

    const int smem_bytes = (16 * H_ + 16384 + 128) * sizeof(float);
    static int smem_set = 0;
    if (!smem_set) {
        cudaFuncSetAttribute(lstm_kernel,
                             cudaFuncAttributeMaxDynamicSharedMemorySize,
                             smem_bytes);
        smem_set = 1;
    }

    init_kernel<<<256, 512>>>(x);
    lstm_kernel<<<GRID_, THREADS_, smem_bytes>>>(Wih, Whh, bih, bhh, out, write_final);
}